// round 1
// baseline (speedup 1.0000x reference)
#include <cuda_runtime.h>

#define P_ 16
#define B_ 4
#define C_ 256
#define N_ 256
#define TJ 64
#define QP 260
#define PP 260
#define VP 17

// 16 MB scratch for corr[p,b,i,d] (d contiguous)
__device__ float g_corr[(size_t)P_ * B_ * N_ * C_];

// ---------------------------------------------------------------------------
// Kernel 1: corr[p,b,i,d] = sum_c tf[p,b,c,i] * We[d,c]
// grid (16, 64): x -> (i-tile, d-tile), y -> p*B+b. 64x64 output tile per CTA.
// ---------------------------------------------------------------------------
__global__ void __launch_bounds__(256) corr_kernel(const float* __restrict__ temp,
                                                   const float* __restrict__ We) {
    __shared__ float sX[16][64];   // [c-chunk][i]
    __shared__ float sW[64][17];   // [d][c-chunk]
    const int t = threadIdx.x;
    const int tx = t & 15, ty = t >> 4;
    const int ti = blockIdx.x & 3, td = blockIdx.x >> 2;
    const int pb = blockIdx.y;
    const float* tf = temp + (size_t)pb * C_ * N_;
    const int i0 = ti * 64, d0 = td * 64;

    float acc[4][4];
#pragma unroll
    for (int u = 0; u < 4; u++)
#pragma unroll
        for (int v = 0; v < 4; v++) acc[u][v] = 0.f;

#pragma unroll 1
    for (int kc = 0; kc < 16; kc++) {
        __syncthreads();
#pragma unroll
        for (int r = 0; r < 4; r++) {
            int e = t + r * 256;
            sX[e >> 6][e & 63] = tf[(kc * 16 + (e >> 6)) * N_ + i0 + (e & 63)];
        }
#pragma unroll
        for (int r = 0; r < 4; r++) {
            int e = t + r * 256;
            sW[e >> 4][e & 15] = We[(size_t)(d0 + (e >> 4)) * C_ + kc * 16 + (e & 15)];
        }
        __syncthreads();
#pragma unroll
        for (int cc = 0; cc < 16; cc++) {
            float a[4], bb[4];
#pragma unroll
            for (int u = 0; u < 4; u++) a[u] = sX[cc][tx * 4 + u];
#pragma unroll
            for (int v = 0; v < 4; v++) bb[v] = sW[ty * 4 + v][cc];
#pragma unroll
            for (int u = 0; u < 4; u++)
#pragma unroll
                for (int v = 0; v < 4; v++) acc[u][v] += a[u] * bb[v];
        }
    }
    float* cr = g_corr + (size_t)pb * N_ * C_;
#pragma unroll
    for (int u = 0; u < 4; u++) {
        int i = i0 + tx * 4 + u;
        float4 w = make_float4(acc[u][0], acc[u][1], acc[u][2], acc[u][3]);
        *(float4*)&cr[(size_t)i * C_ + d0 + ty * 4] = w;
    }
}

__device__ __forceinline__ float inv_patch(const void* p) {
    if (p == nullptr) return 1.f / 16.f;
    int iv = *(const int*)p;
    if (iv >= 1 && iv <= 65536) return 1.f / (float)iv;
    float fv = __int_as_float(iv);
    if (fv >= 0.5f && fv <= 65536.f) return 1.f / fv;
    return 1.f / 16.f;
}

// ---------------------------------------------------------------------------
// Kernel 2: fused per (p, b, j-tile of 64). Loops q = 0..15:
//   A[j,i]   = sum_d corr[p,b,j,d] * tf[q,b,d,i]     (GEMM1, 64x256x256)
//   P[j,:]   = softmax_i(A[j,:])
//   att[c,j] = sum_i tf[q,b,c,i] * P[j,i]            (GEMM2, 256x64x256)
//   mask[j]  = sigmoid(sum_c att[c,j] * Wg[c])
//   out[c,j] += att[c,j] * mask[j]
// Finally out *= 1/patch_num.
// ---------------------------------------------------------------------------
__global__ void __launch_bounds__(256, 1)
fused_kernel(const float* __restrict__ temp,
             const float* __restrict__ Wg,
             const void* __restrict__ pnp,
             float* __restrict__ out) {
    extern __shared__ float sm[];
    float* sQ    = sm;                  // [TJ][QP] corr rows (j0..j0+63, all d)
    float* sP    = sQ + TJ * QP;        // [TJ][PP] A / P; reused as attS[256][64]
    float* sK    = sP + TJ * PP;        // [16][256]  tf d-chunk for GEMM1
    float* sV    = sK + 16 * 256;       // [256][VP]  tf i-chunk for GEMM2
    float* sWg   = sV + 256 * VP;       // [256]
    float* sMask = sWg + 256;           // [64]

    const int t = threadIdx.x;
    const int bid = blockIdx.x;
    const int jt = bid & 3;
    const int b  = (bid >> 2) & 3;
    const int p  = bid >> 4;
    const int j0 = jt * TJ;

    const int tx1 = t & 15, ty1 = t >> 4;   // GEMM1: 4j x 16i micro
    const int tx2 = t & 3,  ty2 = t >> 2;   // GEMM2: 4c x 16j micro (j interleaved)
    const int c0 = ty2 * 4;

    sWg[t] = Wg[t];

    // load Q (corr rows) once
    {
        const float* cr = g_corr + ((size_t)(p * B_ + b) * N_ + j0) * C_;
#pragma unroll 4
        for (int r = 0; r < TJ; r++)
            sQ[r * QP + t] = cr[(size_t)r * C_ + t];
    }

    float outAcc[4][16];
#pragma unroll
    for (int r = 0; r < 4; r++)
#pragma unroll
        for (int k = 0; k < 16; k++) outAcc[r][k] = 0.f;

#pragma unroll 1
    for (int q = 0; q < P_; q++) {
        const float* tfq = temp + (size_t)(q * B_ + b) * C_ * N_;

        // ---- GEMM1: A[j,i] over d ----
        float acc1[4][16];
#pragma unroll
        for (int r = 0; r < 4; r++)
#pragma unroll
            for (int k = 0; k < 16; k++) acc1[r][k] = 0.f;

#pragma unroll 1
        for (int kc = 0; kc < 16; kc++) {
            __syncthreads();
#pragma unroll
            for (int r = 0; r < 16; r++)
                sK[r * 256 + t] = tfq[(size_t)(kc * 16 + r) * N_ + t];
            __syncthreads();
#pragma unroll
            for (int dd = 0; dd < 16; dd++) {
                float a[4];
#pragma unroll
                for (int rr = 0; rr < 4; rr++)
                    a[rr] = sQ[(ty1 * 4 + rr) * QP + kc * 16 + dd];
#pragma unroll
                for (int v = 0; v < 4; v++) {
                    float4 b4 = *(const float4*)&sK[dd * 256 + v * 64 + tx1 * 4];
                    float bv[4] = {b4.x, b4.y, b4.z, b4.w};
#pragma unroll
                    for (int rr = 0; rr < 4; rr++)
#pragma unroll
                        for (int u = 0; u < 4; u++)
                            acc1[rr][v * 4 + u] += a[rr] * bv[u];
                }
            }
        }
        __syncthreads();
        // write A into sP[j][i]
#pragma unroll
        for (int rr = 0; rr < 4; rr++) {
            int j = ty1 * 4 + rr;
#pragma unroll
            for (int v = 0; v < 4; v++) {
                float4 w = make_float4(acc1[rr][v * 4 + 0], acc1[rr][v * 4 + 1],
                                       acc1[rr][v * 4 + 2], acc1[rr][v * 4 + 3]);
                *(float4*)&sP[j * PP + v * 64 + tx1 * 4] = w;
            }
        }
        __syncthreads();

        // ---- softmax rows over i ----
        {
            const int w = t >> 5, l = t & 31;
#pragma unroll 1
            for (int rr = 0; rr < 8; rr++) {
                int j = w * 8 + rr;
                float v[8];
#pragma unroll
                for (int m = 0; m < 8; m++) v[m] = sP[j * PP + l + m * 32];
                float mx = v[0];
#pragma unroll
                for (int m = 1; m < 8; m++) mx = fmaxf(mx, v[m]);
#pragma unroll
                for (int o = 16; o > 0; o >>= 1)
                    mx = fmaxf(mx, __shfl_xor_sync(0xffffffffu, mx, o));
                float s = 0.f;
#pragma unroll
                for (int m = 0; m < 8; m++) { v[m] = __expf(v[m] - mx); s += v[m]; }
#pragma unroll
                for (int o = 16; o > 0; o >>= 1)
                    s += __shfl_xor_sync(0xffffffffu, s, o);
                float inv = 1.f / s;
#pragma unroll
                for (int m = 0; m < 8; m++) sP[j * PP + l + m * 32] = v[m] * inv;
            }
        }
        __syncthreads();

        // ---- GEMM2: att[c,j] over i ----
        float acc2[4][16];
#pragma unroll
        for (int r = 0; r < 4; r++)
#pragma unroll
            for (int k = 0; k < 16; k++) acc2[r][k] = 0.f;

#pragma unroll 1
        for (int kc = 0; kc < 16; kc++) {
#pragma unroll
            for (int r = 0; r < 16; r++) {
                int e = t + r * 256;
                int c = e >> 4, ii = e & 15;
                sV[c * VP + ii] = tfq[(size_t)c * N_ + kc * 16 + ii];
            }
            __syncthreads();
#pragma unroll
            for (int ii = 0; ii < 16; ii++) {
                float vv[4];
#pragma unroll
                for (int r = 0; r < 4; r++) vv[r] = sV[(c0 + r) * VP + ii];
#pragma unroll
                for (int k = 0; k < 16; k++) {
                    float pk = sP[(tx2 + 4 * k) * PP + kc * 16 + ii];
#pragma unroll
                    for (int r = 0; r < 4; r++) acc2[r][k] += vv[r] * pk;
                }
            }
            __syncthreads();
        }

        // ---- stage att into smem (reuse sP) for gate reduction ----
#pragma unroll
        for (int r = 0; r < 4; r++)
#pragma unroll
            for (int k = 0; k < 16; k++)
                sP[(c0 + r) * 64 + (tx2 + 4 * k)] = acc2[r][k];
        __syncthreads();

        // ---- mask[j] = sigmoid(sum_c att[c,j]*Wg[c]) ----
        if (t < 64) {
            float s = 0.f;
#pragma unroll 8
            for (int c = 0; c < 256; c++) s += sP[c * 64 + t] * sWg[c];
            sMask[t] = 1.f / (1.f + __expf(-s));
        }
        __syncthreads();

        // ---- accumulate gated att over q ----
#pragma unroll
        for (int k = 0; k < 16; k++) {
            float m = sMask[tx2 + 4 * k];
#pragma unroll
            for (int r = 0; r < 4; r++) outAcc[r][k] += acc2[r][k] * m;
        }
    }

    // ---- write out ----
    const float invp = inv_patch(pnp);
    float* ob = out + (size_t)(p * B_ + b) * C_ * N_;
#pragma unroll
    for (int r = 0; r < 4; r++) {
        int c = c0 + r;
#pragma unroll
        for (int k = 0; k < 16; k++)
            ob[(size_t)c * N_ + j0 + tx2 + 4 * k] = outAcc[r][k] * invp;
    }
}

// ---------------------------------------------------------------------------
extern "C" void kernel_launch(void* const* d_in, const int* in_sizes, int n_in,
                              void* d_out, int out_size) {
    const float* temp = (const float*)d_in[0];
    const float* We   = (const float*)d_in[1];
    const float* Wg   = (const float*)d_in[2];
    const void*  pn   = (n_in > 3) ? d_in[3] : nullptr;
    float* out = (float*)d_out;

    corr_kernel<<<dim3(16, 64), 256>>>(temp, We);

    const size_t smem = (size_t)(TJ * QP + TJ * PP + 16 * 256 + 256 * VP + 256 + 64) * sizeof(float);
    cudaFuncSetAttribute(fused_kernel, cudaFuncAttributeMaxDynamicSharedMemorySize, (int)smem);
    fused_kernel<<<256, 256, smem>>>(temp, Wg, pn, out);
}

// round 2
// speedup vs baseline: 1.0010x; 1.0010x over previous
#include <cuda_runtime.h>

#define P_ 16
#define B_ 4
#define C_ 256
#define N_ 256
#define TJ 64
#define QP 260
#define PP 260
#define VP 17

// 16 MB scratch for corr[p,b,i,d] (d contiguous)
__device__ float g_corr[(size_t)P_ * B_ * N_ * C_];

// ---------------------------------------------------------------------------
// Kernel 1: corr[p,b,i,d] = sum_c tf[p,b,c,i] * We[d,c]
// grid (16, 64): x -> (i-tile, d-tile), y -> p*B+b. 64x64 output tile per CTA.
// ---------------------------------------------------------------------------
__global__ void __launch_bounds__(256) corr_kernel(const float* __restrict__ temp,
                                                   const float* __restrict__ We) {
    __shared__ float sX[16][64];   // [c-chunk][i]
    __shared__ float sW[64][17];   // [d][c-chunk]
    const int t = threadIdx.x;
    const int tx = t & 15, ty = t >> 4;
    const int ti = blockIdx.x & 3, td = blockIdx.x >> 2;
    const int pb = blockIdx.y;
    const float* tf = temp + (size_t)pb * C_ * N_;
    const int i0 = ti * 64, d0 = td * 64;

    float acc[4][4];
#pragma unroll
    for (int u = 0; u < 4; u++)
#pragma unroll
        for (int v = 0; v < 4; v++) acc[u][v] = 0.f;

#pragma unroll 1
    for (int kc = 0; kc < 16; kc++) {
        __syncthreads();
#pragma unroll
        for (int r = 0; r < 4; r++) {
            int e = t + r * 256;
            sX[e >> 6][e & 63] = tf[(kc * 16 + (e >> 6)) * N_ + i0 + (e & 63)];
        }
#pragma unroll
        for (int r = 0; r < 4; r++) {
            int e = t + r * 256;
            sW[e >> 4][e & 15] = We[(size_t)(d0 + (e >> 4)) * C_ + kc * 16 + (e & 15)];
        }
        __syncthreads();
#pragma unroll
        for (int cc = 0; cc < 16; cc++) {
            float a[4], bb[4];
#pragma unroll
            for (int u = 0; u < 4; u++) a[u] = sX[cc][tx * 4 + u];
#pragma unroll
            for (int v = 0; v < 4; v++) bb[v] = sW[ty * 4 + v][cc];
#pragma unroll
            for (int u = 0; u < 4; u++)
#pragma unroll
                for (int v = 0; v < 4; v++) acc[u][v] += a[u] * bb[v];
        }
    }
    float* cr = g_corr + (size_t)pb * N_ * C_;
#pragma unroll
    for (int u = 0; u < 4; u++) {
        int i = i0 + tx * 4 + u;
        float4 w = make_float4(acc[u][0], acc[u][1], acc[u][2], acc[u][3]);
        *(float4*)&cr[(size_t)i * C_ + d0 + ty * 4] = w;
    }
}

__device__ __forceinline__ float inv_patch(const void* p) {
    if (p == nullptr) return 1.f / 16.f;
    int iv = *(const int*)p;
    if (iv >= 1 && iv <= 65536) return 1.f / (float)iv;
    float fv = __int_as_float(iv);
    if (fv >= 0.5f && fv <= 65536.f) return 1.f / fv;
    return 1.f / 16.f;
}

// ---------------------------------------------------------------------------
// Kernel 2: fused per (p, b, j-tile of 64). Loops q = 0..15:
//   A[j,i]   = sum_d corr[p,b,j,d] * tf[q,b,d,i]     (GEMM1, 64x256x256)
//   P[j,:]   = softmax_i(A[j,:])
//   att[c,j] = sum_i tf[q,b,c,i] * P[j,i]            (GEMM2, 256x64x256)
//   mask[j]  = sigmoid(sum_c att[c,j] * Wg[c])
//   out[c,j] += att[c,j] * mask[j]
// Finally out *= 1/patch_num.
// ---------------------------------------------------------------------------
__global__ void __launch_bounds__(256, 1)
fused_kernel(const float* __restrict__ temp,
             const float* __restrict__ Wg,
             const void* __restrict__ pnp,
             float* __restrict__ out) {
    extern __shared__ float sm[];
    float* sQ    = sm;                  // [TJ][QP] corr rows (j0..j0+63, all d)
    float* sP    = sQ + TJ * QP;        // [TJ][PP] A / P; reused as attS[256][64]
    float* sK    = sP + TJ * PP;        // [16][256]  tf d-chunk for GEMM1
    float* sV    = sK + 16 * 256;       // [256][VP]  tf i-chunk for GEMM2
    float* sWg   = sV + 256 * VP;       // [256]
    float* sMask = sWg + 256;           // [64]

    const int t = threadIdx.x;
    const int bid = blockIdx.x;
    const int jt = bid & 3;
    const int b  = (bid >> 2) & 3;
    const int p  = bid >> 4;
    const int j0 = jt * TJ;

    const int tx1 = t & 15, ty1 = t >> 4;   // GEMM1: 4j x 16i micro
    const int tx2 = t & 3,  ty2 = t >> 2;   // GEMM2: 4c x 16j micro (j interleaved)
    const int c0 = ty2 * 4;

    sWg[t] = Wg[t];

    // load Q (corr rows) once
    {
        const float* cr = g_corr + ((size_t)(p * B_ + b) * N_ + j0) * C_;
#pragma unroll 4
        for (int r = 0; r < TJ; r++)
            sQ[r * QP + t] = cr[(size_t)r * C_ + t];
    }

    float outAcc[4][16];
#pragma unroll
    for (int r = 0; r < 4; r++)
#pragma unroll
        for (int k = 0; k < 16; k++) outAcc[r][k] = 0.f;

#pragma unroll 1
    for (int q = 0; q < P_; q++) {
        const float* tfq = temp + (size_t)(q * B_ + b) * C_ * N_;

        // ---- GEMM1: A[j,i] over d ----
        float acc1[4][16];
#pragma unroll
        for (int r = 0; r < 4; r++)
#pragma unroll
            for (int k = 0; k < 16; k++) acc1[r][k] = 0.f;

#pragma unroll 1
        for (int kc = 0; kc < 16; kc++) {
            __syncthreads();
#pragma unroll
            for (int r = 0; r < 16; r++)
                sK[r * 256 + t] = tfq[(size_t)(kc * 16 + r) * N_ + t];
            __syncthreads();
#pragma unroll
            for (int dd = 0; dd < 16; dd++) {
                float a[4];
#pragma unroll
                for (int rr = 0; rr < 4; rr++)
                    a[rr] = sQ[(ty1 * 4 + rr) * QP + kc * 16 + dd];
#pragma unroll
                for (int v = 0; v < 4; v++) {
                    float4 b4 = *(const float4*)&sK[dd * 256 + v * 64 + tx1 * 4];
                    float bv[4] = {b4.x, b4.y, b4.z, b4.w};
#pragma unroll
                    for (int rr = 0; rr < 4; rr++)
#pragma unroll
                        for (int u = 0; u < 4; u++)
                            acc1[rr][v * 4 + u] += a[rr] * bv[u];
                }
            }
        }
        __syncthreads();
        // write A into sP[j][i]
#pragma unroll
        for (int rr = 0; rr < 4; rr++) {
            int j = ty1 * 4 + rr;
#pragma unroll
            for (int v = 0; v < 4; v++) {
                float4 w = make_float4(acc1[rr][v * 4 + 0], acc1[rr][v * 4 + 1],
                                       acc1[rr][v * 4 + 2], acc1[rr][v * 4 + 3]);
                *(float4*)&sP[j * PP + v * 64 + tx1 * 4] = w;
            }
        }
        __syncthreads();

        // ---- softmax rows over i ----
        {
            const int w = t >> 5, l = t & 31;
#pragma unroll 1
            for (int rr = 0; rr < 8; rr++) {
                int j = w * 8 + rr;
                float v[8];
#pragma unroll
                for (int m = 0; m < 8; m++) v[m] = sP[j * PP + l + m * 32];
                float mx = v[0];
#pragma unroll
                for (int m = 1; m < 8; m++) mx = fmaxf(mx, v[m]);
#pragma unroll
                for (int o = 16; o > 0; o >>= 1)
                    mx = fmaxf(mx, __shfl_xor_sync(0xffffffffu, mx, o));
                float s = 0.f;
#pragma unroll
                for (int m = 0; m < 8; m++) { v[m] = __expf(v[m] - mx); s += v[m]; }
#pragma unroll
                for (int o = 16; o > 0; o >>= 1)
                    s += __shfl_xor_sync(0xffffffffu, s, o);
                float inv = 1.f / s;
#pragma unroll
                for (int m = 0; m < 8; m++) sP[j * PP + l + m * 32] = v[m] * inv;
            }
        }
        __syncthreads();

        // ---- GEMM2: att[c,j] over i ----
        float acc2[4][16];
#pragma unroll
        for (int r = 0; r < 4; r++)
#pragma unroll
            for (int k = 0; k < 16; k++) acc2[r][k] = 0.f;

#pragma unroll 1
        for (int kc = 0; kc < 16; kc++) {
#pragma unroll
            for (int r = 0; r < 16; r++) {
                int e = t + r * 256;
                int c = e >> 4, ii = e & 15;
                sV[c * VP + ii] = tfq[(size_t)c * N_ + kc * 16 + ii];
            }
            __syncthreads();
#pragma unroll
            for (int ii = 0; ii < 16; ii++) {
                float vv[4];
#pragma unroll
                for (int r = 0; r < 4; r++) vv[r] = sV[(c0 + r) * VP + ii];
#pragma unroll
                for (int k = 0; k < 16; k++) {
                    float pk = sP[(tx2 + 4 * k) * PP + kc * 16 + ii];
#pragma unroll
                    for (int r = 0; r < 4; r++) acc2[r][k] += vv[r] * pk;
                }
            }
            __syncthreads();
        }

        // ---- stage att into smem (reuse sP) for gate reduction ----
#pragma unroll
        for (int r = 0; r < 4; r++)
#pragma unroll
            for (int k = 0; k < 16; k++)
                sP[(c0 + r) * 64 + (tx2 + 4 * k)] = acc2[r][k];
        __syncthreads();

        // ---- mask[j] = sigmoid(sum_c att[c,j]*Wg[c]) ----
        if (t < 64) {
            float s = 0.f;
#pragma unroll 8
            for (int c = 0; c < 256; c++) s += sP[c * 64 + t] * sWg[c];
            sMask[t] = 1.f / (1.f + __expf(-s));
        }
        __syncthreads();

        // ---- accumulate gated att over q ----
#pragma unroll
        for (int k = 0; k < 16; k++) {
            float m = sMask[tx2 + 4 * k];
#pragma unroll
            for (int r = 0; r < 4; r++) outAcc[r][k] += acc2[r][k] * m;
        }
    }

    // ---- write out ----
    const float invp = inv_patch(pnp);
    float* ob = out + (size_t)(p * B_ + b) * C_ * N_;
#pragma unroll
    for (int r = 0; r < 4; r++) {
        int c = c0 + r;
#pragma unroll
        for (int k = 0; k < 16; k++)
            ob[(size_t)c * N_ + j0 + tx2 + 4 * k] = outAcc[r][k] * invp;
    }
}

// ---------------------------------------------------------------------------
extern "C" void kernel_launch(void* const* d_in, const int* in_sizes, int n_in,
                              void* d_out, int out_size) {
    const float* temp = (const float*)d_in[0];
    const float* We   = (const float*)d_in[1];
    const float* Wg   = (const float*)d_in[2];
    const void*  pn   = (n_in > 3) ? d_in[3] : nullptr;
    float* out = (float*)d_out;

    corr_kernel<<<dim3(16, 64), 256>>>(temp, We);

    const size_t smem = (size_t)(TJ * QP + TJ * PP + 16 * 256 + 256 * VP + 256 + 64) * sizeof(float);
    cudaFuncSetAttribute(fused_kernel, cudaFuncAttributeMaxDynamicSharedMemorySize, (int)smem);
    fused_kernel<<<256, 256, smem>>>(temp, Wg, pn, out);
}

// round 3
// speedup vs baseline: 1.0021x; 1.0011x over previous
#include <cuda_runtime.h>

#define P_ 16
#define B_ 4
#define C_ 256
#define N_ 256
#define TJ 64
#define QP 260
#define PP 260
#define VP 17

// 16 MB scratch for corr[p,b,i,d] (d contiguous)
__device__ float g_corr[(size_t)P_ * B_ * N_ * C_];

// ---------------------------------------------------------------------------
// Kernel 1: corr[p,b,i,d] = sum_c tf[p,b,c,i] * We[d,c]
// grid (16, 64): x -> (i-tile, d-tile), y -> p*B+b. 64x64 output tile per CTA.
// ---------------------------------------------------------------------------
__global__ void __launch_bounds__(256) corr_kernel(const float* __restrict__ temp,
                                                   const float* __restrict__ We) {
    __shared__ float sX[16][64];   // [c-chunk][i]
    __shared__ float sW[64][17];   // [d][c-chunk]
    const int t = threadIdx.x;
    const int tx = t & 15, ty = t >> 4;
    const int ti = blockIdx.x & 3, td = blockIdx.x >> 2;
    const int pb = blockIdx.y;
    const float* tf = temp + (size_t)pb * C_ * N_;
    const int i0 = ti * 64, d0 = td * 64;

    float acc[4][4];
#pragma unroll
    for (int u = 0; u < 4; u++)
#pragma unroll
        for (int v = 0; v < 4; v++) acc[u][v] = 0.f;

#pragma unroll 1
    for (int kc = 0; kc < 16; kc++) {
        __syncthreads();
#pragma unroll
        for (int r = 0; r < 4; r++) {
            int e = t + r * 256;
            sX[e >> 6][e & 63] = tf[(kc * 16 + (e >> 6)) * N_ + i0 + (e & 63)];
        }
#pragma unroll
        for (int r = 0; r < 4; r++) {
            int e = t + r * 256;
            sW[e >> 4][e & 15] = We[(size_t)(d0 + (e >> 4)) * C_ + kc * 16 + (e & 15)];
        }
        __syncthreads();
#pragma unroll
        for (int cc = 0; cc < 16; cc++) {
            float a[4], bb[4];
#pragma unroll
            for (int u = 0; u < 4; u++) a[u] = sX[cc][tx * 4 + u];
#pragma unroll
            for (int v = 0; v < 4; v++) bb[v] = sW[ty * 4 + v][cc];
#pragma unroll
            for (int u = 0; u < 4; u++)
#pragma unroll
                for (int v = 0; v < 4; v++) acc[u][v] += a[u] * bb[v];
        }
    }
    float* cr = g_corr + (size_t)pb * N_ * C_;
#pragma unroll
    for (int u = 0; u < 4; u++) {
        int i = i0 + tx * 4 + u;
        float4 w = make_float4(acc[u][0], acc[u][1], acc[u][2], acc[u][3]);
        *(float4*)&cr[(size_t)i * C_ + d0 + ty * 4] = w;
    }
}

__device__ __forceinline__ float inv_patch(const void* p) {
    if (p == nullptr) return 1.f / 16.f;
    int iv = *(const int*)p;
    if (iv >= 1 && iv <= 65536) return 1.f / (float)iv;
    float fv = __int_as_float(iv);
    if (fv >= 0.5f && fv <= 65536.f) return 1.f / fv;
    return 1.f / 16.f;
}

// ---------------------------------------------------------------------------
// Kernel 2: fused per (p, b, j-tile of 64). Loops q = 0..15:
//   A[j,i]   = sum_d corr[p,b,j,d] * tf[q,b,d,i]     (GEMM1, 64x256x256)
//   P[j,:]   = softmax_i(A[j,:])
//   att[c,j] = sum_i tf[q,b,c,i] * P[j,i]            (GEMM2, 256x64x256)
//   mask[j]  = sigmoid(sum_c att[c,j] * Wg[c])
//   out[c,j] += att[c,j] * mask[j]
// Finally out *= 1/patch_num.
// ---------------------------------------------------------------------------
__global__ void __launch_bounds__(256, 1)
fused_kernel(const float* __restrict__ temp,
             const float* __restrict__ Wg,
             const void* __restrict__ pnp,
             float* __restrict__ out) {
    extern __shared__ float sm[];
    float* sQ    = sm;                  // [TJ][QP] corr rows (j0..j0+63, all d)
    float* sP    = sQ + TJ * QP;        // [TJ][PP] A / P; reused as attS[256][64]
    float* sK    = sP + TJ * PP;        // [16][256]  tf d-chunk for GEMM1
    float* sV    = sK + 16 * 256;       // [256][VP]  tf i-chunk for GEMM2
    float* sWg   = sV + 256 * VP;       // [256]
    float* sMask = sWg + 256;           // [64]

    const int t = threadIdx.x;
    const int bid = blockIdx.x;
    const int jt = bid & 3;
    const int b  = (bid >> 2) & 3;
    const int p  = bid >> 4;
    const int j0 = jt * TJ;

    const int tx1 = t & 15, ty1 = t >> 4;   // GEMM1: 4j x 16i micro
    const int tx2 = t & 3,  ty2 = t >> 2;   // GEMM2: 4c x 16j micro (j interleaved)
    const int c0 = ty2 * 4;

    sWg[t] = Wg[t];

    // load Q (corr rows) once
    {
        const float* cr = g_corr + ((size_t)(p * B_ + b) * N_ + j0) * C_;
#pragma unroll 4
        for (int r = 0; r < TJ; r++)
            sQ[r * QP + t] = cr[(size_t)r * C_ + t];
    }

    float outAcc[4][16];
#pragma unroll
    for (int r = 0; r < 4; r++)
#pragma unroll
        for (int k = 0; k < 16; k++) outAcc[r][k] = 0.f;

#pragma unroll 1
    for (int q = 0; q < P_; q++) {
        const float* tfq = temp + (size_t)(q * B_ + b) * C_ * N_;

        // ---- GEMM1: A[j,i] over d ----
        float acc1[4][16];
#pragma unroll
        for (int r = 0; r < 4; r++)
#pragma unroll
            for (int k = 0; k < 16; k++) acc1[r][k] = 0.f;

#pragma unroll 1
        for (int kc = 0; kc < 16; kc++) {
            __syncthreads();
#pragma unroll
            for (int r = 0; r < 16; r++)
                sK[r * 256 + t] = tfq[(size_t)(kc * 16 + r) * N_ + t];
            __syncthreads();
#pragma unroll
            for (int dd = 0; dd < 16; dd++) {
                float a[4];
#pragma unroll
                for (int rr = 0; rr < 4; rr++)
                    a[rr] = sQ[(ty1 * 4 + rr) * QP + kc * 16 + dd];
#pragma unroll
                for (int v = 0; v < 4; v++) {
                    float4 b4 = *(const float4*)&sK[dd * 256 + v * 64 + tx1 * 4];
                    float bv[4] = {b4.x, b4.y, b4.z, b4.w};
#pragma unroll
                    for (int rr = 0; rr < 4; rr++)
#pragma unroll
                        for (int u = 0; u < 4; u++)
                            acc1[rr][v * 4 + u] += a[rr] * bv[u];
                }
            }
        }
        __syncthreads();
        // write A into sP[j][i]
#pragma unroll
        for (int rr = 0; rr < 4; rr++) {
            int j = ty1 * 4 + rr;
#pragma unroll
            for (int v = 0; v < 4; v++) {
                float4 w = make_float4(acc1[rr][v * 4 + 0], acc1[rr][v * 4 + 1],
                                       acc1[rr][v * 4 + 2], acc1[rr][v * 4 + 3]);
                *(float4*)&sP[j * PP + v * 64 + tx1 * 4] = w;
            }
        }
        __syncthreads();

        // ---- softmax rows over i ----
        {
            const int w = t >> 5, l = t & 31;
#pragma unroll 1
            for (int rr = 0; rr < 8; rr++) {
                int j = w * 8 + rr;
                float v[8];
#pragma unroll
                for (int m = 0; m < 8; m++) v[m] = sP[j * PP + l + m * 32];
                float mx = v[0];
#pragma unroll
                for (int m = 1; m < 8; m++) mx = fmaxf(mx, v[m]);
#pragma unroll
                for (int o = 16; o > 0; o >>= 1)
                    mx = fmaxf(mx, __shfl_xor_sync(0xffffffffu, mx, o));
                float s = 0.f;
#pragma unroll
                for (int m = 0; m < 8; m++) { v[m] = __expf(v[m] - mx); s += v[m]; }
#pragma unroll
                for (int o = 16; o > 0; o >>= 1)
                    s += __shfl_xor_sync(0xffffffffu, s, o);
                float inv = 1.f / s;
#pragma unroll
                for (int m = 0; m < 8; m++) sP[j * PP + l + m * 32] = v[m] * inv;
            }
        }
        __syncthreads();

        // ---- GEMM2: att[c,j] over i ----
        float acc2[4][16];
#pragma unroll
        for (int r = 0; r < 4; r++)
#pragma unroll
            for (int k = 0; k < 16; k++) acc2[r][k] = 0.f;

#pragma unroll 1
        for (int kc = 0; kc < 16; kc++) {
#pragma unroll
            for (int r = 0; r < 16; r++) {
                int e = t + r * 256;
                int c = e >> 4, ii = e & 15;
                sV[c * VP + ii] = tfq[(size_t)c * N_ + kc * 16 + ii];
            }
            __syncthreads();
#pragma unroll
            for (int ii = 0; ii < 16; ii++) {
                float vv[4];
#pragma unroll
                for (int r = 0; r < 4; r++) vv[r] = sV[(c0 + r) * VP + ii];
#pragma unroll
                for (int k = 0; k < 16; k++) {
                    float pk = sP[(tx2 + 4 * k) * PP + kc * 16 + ii];
#pragma unroll
                    for (int r = 0; r < 4; r++) acc2[r][k] += vv[r] * pk;
                }
            }
            __syncthreads();
        }

        // ---- stage att into smem (reuse sP) for gate reduction ----
#pragma unroll
        for (int r = 0; r < 4; r++)
#pragma unroll
            for (int k = 0; k < 16; k++)
                sP[(c0 + r) * 64 + (tx2 + 4 * k)] = acc2[r][k];
        __syncthreads();

        // ---- mask[j] = sigmoid(sum_c att[c,j]*Wg[c]) ----
        if (t < 64) {
            float s = 0.f;
#pragma unroll 8
            for (int c = 0; c < 256; c++) s += sP[c * 64 + t] * sWg[c];
            sMask[t] = 1.f / (1.f + __expf(-s));
        }
        __syncthreads();

        // ---- accumulate gated att over q ----
#pragma unroll
        for (int k = 0; k < 16; k++) {
            float m = sMask[tx2 + 4 * k];
#pragma unroll
            for (int r = 0; r < 4; r++) outAcc[r][k] += acc2[r][k] * m;
        }
    }

    // ---- write out ----
    const float invp = inv_patch(pnp);
    float* ob = out + (size_t)(p * B_ + b) * C_ * N_;
#pragma unroll
    for (int r = 0; r < 4; r++) {
        int c = c0 + r;
#pragma unroll
        for (int k = 0; k < 16; k++)
            ob[(size_t)c * N_ + j0 + tx2 + 4 * k] = outAcc[r][k] * invp;
    }
}

// ---------------------------------------------------------------------------
extern "C" void kernel_launch(void* const* d_in, const int* in_sizes, int n_in,
                              void* d_out, int out_size) {
    const float* temp = (const float*)d_in[0];
    const float* We   = (const float*)d_in[1];
    const float* Wg   = (const float*)d_in[2];
    const void*  pn   = (n_in > 3) ? d_in[3] : nullptr;
    float* out = (float*)d_out;

    corr_kernel<<<dim3(16, 64), 256>>>(temp, We);

    const size_t smem = (size_t)(TJ * QP + TJ * PP + 16 * 256 + 256 * VP + 256 + 64) * sizeof(float);
    cudaFuncSetAttribute(fused_kernel, cudaFuncAttributeMaxDynamicSharedMemorySize, (int)smem);
    fused_kernel<<<256, 256, smem>>>(temp, Wg, pn, out);
}